// round 5
// baseline (speedup 1.0000x reference)
#include <cuda_runtime.h>
#include <cuda_fp16.h>
#include <cstdint>

#define NN     20000
#define EE     640000
#define ETOT   660000      // EE + NN self loops
#define GG     64
#define FIN    128
#define FOUT   128
#define HEADS  4
#define HID    64
#define HC12   256         // HEADS*HID

// ---------------------------------------------------------------------------
// Scratch (device globals)
// ---------------------------------------------------------------------------
__device__ __half g_h16[(size_t)NN * HC12];   // h = x @ W (fp16, gather input)
__device__ float  g_bufB[(size_t)NN * HC12];  // aggregated out (fp32)
__device__ float  g_as[(size_t)NN * HEADS];
__device__ float  g_ad[(size_t)NN * HEADS];
__device__ float  g_gsum[GG * FOUT];
__device__ float  g_gcnt[GG];
__device__ int    g_deg[NN];
__device__ int    g_off[NN + 1];
__device__ int    g_cur[NN];
__device__ int    g_csr_src[ETOT];

// ---------------------------------------------------------------------------
// TF32 helpers
// ---------------------------------------------------------------------------
__device__ __forceinline__ float to_tf32(float x) {
    uint32_t u;
    asm("cvt.rna.tf32.f32 %0, %1;" : "=r"(u) : "f"(x));
    return __uint_as_float(u);
}

__device__ __forceinline__ void mma_tf32(float* c, const uint32_t* a, const uint32_t* b) {
    asm volatile(
        "mma.sync.aligned.m16n8k8.row.col.f32.tf32.tf32.f32 "
        "{%0,%1,%2,%3}, {%4,%5,%6,%7}, {%8,%9}, {%0,%1,%2,%3};"
        : "+f"(c[0]), "+f"(c[1]), "+f"(c[2]), "+f"(c[3])
        : "r"(a[0]), "r"(a[1]), "r"(a[2]), "r"(a[3]), "r"(b[0]), "r"(b[1]));
}

// ---------------------------------------------------------------------------
// TF32 tensor-core GEMM: C[N,M] = A[N,K] * B[K,M], fp16 output.
// BM=128, BN=64, BK=16; 8 warps, each 32x32; mma m16n8k8.
// ---------------------------------------------------------------------------
__global__ __launch_bounds__(256) void gemm_tc_kernel(
    const float* __restrict__ A, const float* __restrict__ B,
    __half* __restrict__ C, int N, int K, int M)
{
    __shared__ float As[128][20];
    __shared__ float Bs[16][72];

    const int tid  = threadIdx.x;
    const int lane = tid & 31;
    const int warp = tid >> 5;
    const int wr   = (warp & 3) * 32;
    const int wc   = (warp >> 2) * 32;
    const int rowBase = blockIdx.y * 128;
    const int colBase = blockIdx.x * 64;
    const int g  = lane >> 2;
    const int tg = lane & 3;

    float acc[2][4][4];
#pragma unroll
    for (int i = 0; i < 2; i++)
#pragma unroll
        for (int j = 0; j < 4; j++)
#pragma unroll
            for (int k = 0; k < 4; k++) acc[i][j][k] = 0.f;

    for (int k0 = 0; k0 < K; k0 += 16) {
#pragma unroll
        for (int l = 0; l < 2; l++) {
            int i  = tid + l * 256;
            int r  = i >> 2;
            int c4 = (i & 3) * 4;
            int gr = rowBase + r;
            float4 v = make_float4(0.f, 0.f, 0.f, 0.f);
            if (gr < N) v = *reinterpret_cast<const float4*>(&A[(size_t)gr * K + k0 + c4]);
            v.x = to_tf32(v.x); v.y = to_tf32(v.y);
            v.z = to_tf32(v.z); v.w = to_tf32(v.w);
            *reinterpret_cast<float4*>(&As[r][c4]) = v;
        }
        {
            int r  = tid >> 4;
            int c4 = (tid & 15) * 4;
            float4 v = *reinterpret_cast<const float4*>(&B[(size_t)(k0 + r) * M + colBase + c4]);
            v.x = to_tf32(v.x); v.y = to_tf32(v.y);
            v.z = to_tf32(v.z); v.w = to_tf32(v.w);
            *reinterpret_cast<float4*>(&Bs[r][c4]) = v;
        }
        __syncthreads();

#pragma unroll
        for (int kk = 0; kk < 16; kk += 8) {
            uint32_t a[2][4], b[4][2];
#pragma unroll
            for (int i = 0; i < 2; i++) {
                int r0 = wr + i * 16 + g;
                a[i][0] = __float_as_uint(As[r0][kk + tg]);
                a[i][1] = __float_as_uint(As[r0 + 8][kk + tg]);
                a[i][2] = __float_as_uint(As[r0][kk + 4 + tg]);
                a[i][3] = __float_as_uint(As[r0 + 8][kk + 4 + tg]);
            }
#pragma unroll
            for (int j = 0; j < 4; j++) {
                int c0 = wc + j * 8 + g;
                b[j][0] = __float_as_uint(Bs[kk + tg][c0]);
                b[j][1] = __float_as_uint(Bs[kk + 4 + tg][c0]);
            }
#pragma unroll
            for (int i = 0; i < 2; i++)
#pragma unroll
                for (int j = 0; j < 4; j++)
                    mma_tf32(acc[i][j], a[i], b[j]);
        }
        __syncthreads();
    }

#pragma unroll
    for (int i = 0; i < 2; i++) {
        int r0 = rowBase + wr + i * 16 + g;
#pragma unroll
        for (int j = 0; j < 4; j++) {
            int c0 = colBase + wc + j * 8 + tg * 2;
            if (r0 < N) {
                __half2 v = __floats2half2_rn(acc[i][j][0], acc[i][j][1]);
                *reinterpret_cast<__half2*>(&C[(size_t)r0 * M + c0]) = v;
            }
            if (r0 + 8 < N) {
                __half2 v = __floats2half2_rn(acc[i][j][2], acc[i][j][3]);
                *reinterpret_cast<__half2*>(&C[(size_t)(r0 + 8) * M + c0]) = v;
            }
        }
    }
}

// ---------------------------------------------------------------------------
// CSR build: histogram -> fast scan -> scatter
// ---------------------------------------------------------------------------
__global__ void csr_count_kernel(const int* __restrict__ ei, int* __restrict__ deg)
{
    int t = blockIdx.x * blockDim.x + threadIdx.x;
    if (t >= ETOT) return;
    int d = (t < EE) ? ei[EE + t] : (t - EE);
    atomicAdd(&deg[d], 1);
}

__global__ __launch_bounds__(1024) void csr_scan_kernel(
    const int* __restrict__ deg, int* __restrict__ off, int* __restrict__ cur)
{
    const int PER = 20;
    __shared__ int warpSums[32];
    int t    = threadIdx.x;
    int lane = t & 31, wid = t >> 5;
    int base = t * PER;

    int v[PER];
    int s = 0;
#pragma unroll
    for (int i = 0; i < PER; i++) {
        int idx = base + i;
        int x = (idx < NN) ? deg[idx] : 0;
        v[i] = s;
        s += x;
    }
    int incl = s;
#pragma unroll
    for (int o = 1; o < 32; o <<= 1) {
        int u = __shfl_up_sync(0xffffffffu, incl, o);
        if (lane >= o) incl += u;
    }
    if (lane == 31) warpSums[wid] = incl;
    __syncthreads();
    if (wid == 0) {
        int ws = warpSums[lane];
#pragma unroll
        for (int o = 1; o < 32; o <<= 1) {
            int u = __shfl_up_sync(0xffffffffu, ws, o);
            if (lane >= o) ws += u;
        }
        warpSums[lane] = ws;
    }
    __syncthreads();
    int warpPrefix  = (wid == 0) ? 0 : warpSums[wid - 1];
    int threadExcl  = warpPrefix + incl - s;
#pragma unroll
    for (int i = 0; i < PER; i++) {
        int idx = base + i;
        if (idx < NN) {
            int e = threadExcl + v[i];
            off[idx] = e;
            cur[idx] = e;
        }
    }
    if (t == 0) off[NN] = ETOT;
}

__global__ void csr_scatter_kernel(const int* __restrict__ ei,
                                   int* __restrict__ cur, int* __restrict__ csr_src)
{
    int t = blockIdx.x * blockDim.x + threadIdx.x;
    if (t >= ETOT) return;
    int s, d;
    if (t < EE) { s = ei[t]; d = ei[EE + t]; }
    else        { s = t - EE; d = s; }
    int pos = atomicAdd(&cur[d], 1);
    csr_src[pos] = s;
}

// ---------------------------------------------------------------------------
// alpha_s / alpha_d from fp16 h: warp per (node, head)
// ---------------------------------------------------------------------------
__global__ void alpha_kernel(const __half* __restrict__ h,
                             const float* __restrict__ a_s,
                             const float* __restrict__ a_d,
                             float* __restrict__ outs, float* __restrict__ outd,
                             int H, int C)
{
    int gt   = blockIdx.x * blockDim.x + threadIdx.x;
    int wid  = gt >> 5;
    int lane = gt & 31;
    if (wid >= NN * H) return;
    int i  = wid / H;
    int hh = wid - i * H;
    const __half* hp = h + (size_t)i * H * C + hh * C;
    const float* asp = a_s + hh * C;
    const float* adp = a_d + hh * C;
    float ss = 0.f, sd = 0.f;
    for (int c = lane * 2; c < C; c += 64) {
        __half2 hv = *reinterpret_cast<const __half2*>(&hp[c]);
        float2 f = __half22float2(hv);
        ss += f.x * asp[c] + f.y * asp[c + 1];
        sd += f.x * adp[c] + f.y * adp[c + 1];
    }
#pragma unroll
    for (int o = 16; o; o >>= 1) {
        ss += __shfl_xor_sync(0xffffffffu, ss, o);
        sd += __shfl_xor_sync(0xffffffffu, sd, o);
    }
    if (lane == 0) { outs[wid] = ss; outd[wid] = sd; }
}

// ---------------------------------------------------------------------------
// Fused GAT aggregation (H=4, C=64), fp16 h: warp per dst node.
// Lane l owns channels [8l, 8l+8) -> single head l>>3.
// ---------------------------------------------------------------------------
__global__ __launch_bounds__(256) void gat_gather4_kernel(
    const int* __restrict__ off, const int* __restrict__ csr_src,
    const __half* __restrict__ h,
    const float* __restrict__ as_, const float* __restrict__ ad_,
    const float* __restrict__ bias, float* __restrict__ out, int do_elu)
{
    int gt   = blockIdx.x * blockDim.x + threadIdx.x;
    int d    = gt >> 5;
    int lane = gt & 31;
    if (d >= NN) return;

    const int head = lane >> 3;
    float4 ad4 = *reinterpret_cast<const float4*>(&ad_[d * 4]);
    float adv = (head == 0) ? ad4.x : (head == 1) ? ad4.y : (head == 2) ? ad4.z : ad4.w;

    float acc[8];
#pragma unroll
    for (int k = 0; k < 8; k++) acc[k] = 0.f;
    float den = 0.f;

    int a   = off[d];
    int end = off[d + 1];
    for (; a < end; a++) {
        int s = csr_src[a];
        float4 as4 = *reinterpret_cast<const float4*>(&as_[s * 4]);
        float e = ((head == 0) ? as4.x : (head == 1) ? as4.y : (head == 2) ? as4.z : as4.w) + adv;
        e = e > 0.f ? e : 0.2f * e;
        float ex = __expf(e);
        uint4 v = reinterpret_cast<const uint4*>(h + (size_t)s * HC12)[lane];
        float2 f0 = __half22float2(*reinterpret_cast<__half2*>(&v.x));
        float2 f1 = __half22float2(*reinterpret_cast<__half2*>(&v.y));
        float2 f2 = __half22float2(*reinterpret_cast<__half2*>(&v.z));
        float2 f3 = __half22float2(*reinterpret_cast<__half2*>(&v.w));
        acc[0] += ex * f0.x; acc[1] += ex * f0.y;
        acc[2] += ex * f1.x; acc[3] += ex * f1.y;
        acc[4] += ex * f2.x; acc[5] += ex * f2.y;
        acc[6] += ex * f3.x; acc[7] += ex * f3.y;
        den += ex;
    }

    float r = 1.f / (den + 1e-16f);
    float4 b0 = *reinterpret_cast<const float4*>(&bias[lane * 8]);
    float4 b1 = *reinterpret_cast<const float4*>(&bias[lane * 8 + 4]);
    float o[8];
    o[0] = acc[0] * r + b0.x; o[1] = acc[1] * r + b0.y;
    o[2] = acc[2] * r + b0.z; o[3] = acc[3] * r + b0.w;
    o[4] = acc[4] * r + b1.x; o[5] = acc[5] * r + b1.y;
    o[6] = acc[6] * r + b1.z; o[7] = acc[7] * r + b1.w;
    if (do_elu) {
#pragma unroll
        for (int k = 0; k < 8; k++) o[k] = o[k] > 0.f ? o[k] : expm1f(o[k]);
    }
    float4* op = reinterpret_cast<float4*>(out + (size_t)d * HC12 + lane * 8);
    op[0] = make_float4(o[0], o[1], o[2], o[3]);
    op[1] = make_float4(o[4], o[5], o[6], o[7]);
}

// ---------------------------------------------------------------------------
// Fused GAT aggregation (H=1, C=128), fp16 h: warp per dst, lane owns 4 chans.
// ---------------------------------------------------------------------------
__global__ __launch_bounds__(256) void gat_gather1_kernel(
    const int* __restrict__ off, const int* __restrict__ csr_src,
    const __half* __restrict__ h,
    const float* __restrict__ as_, const float* __restrict__ ad_,
    const float* __restrict__ bias, float* __restrict__ out)
{
    int gt   = blockIdx.x * blockDim.x + threadIdx.x;
    int d    = gt >> 5;
    int lane = gt & 31;
    if (d >= NN) return;

    float adv = ad_[d];
    float acc[4] = {0.f, 0.f, 0.f, 0.f};
    float den = 0.f;

    int a   = off[d];
    int end = off[d + 1];
    for (; a < end; a++) {
        int s = csr_src[a];
        float e = as_[s] + adv;
        e = e > 0.f ? e : 0.2f * e;
        float ex = __expf(e);
        uint2 v = reinterpret_cast<const uint2*>(h + (size_t)s * FOUT)[lane];
        float2 f0 = __half22float2(*reinterpret_cast<__half2*>(&v.x));
        float2 f1 = __half22float2(*reinterpret_cast<__half2*>(&v.y));
        acc[0] += ex * f0.x; acc[1] += ex * f0.y;
        acc[2] += ex * f1.x; acc[3] += ex * f1.y;
        den += ex;
    }

    float r = 1.f / (den + 1e-16f);
    float4 b = *reinterpret_cast<const float4*>(&bias[lane * 4]);
    float4 o;
    o.x = acc[0] * r + b.x; o.y = acc[1] * r + b.y;
    o.z = acc[2] * r + b.z; o.w = acc[3] * r + b.w;
    reinterpret_cast<float4*>(out + (size_t)d * FOUT)[lane] = o;
}

// ---------------------------------------------------------------------------
// Global mean pool
// ---------------------------------------------------------------------------
__global__ void pool_cnt_kernel(const int* __restrict__ batch, float* __restrict__ cnt)
{
    int t = blockIdx.x * blockDim.x + threadIdx.x;
    if (t >= NN) return;
    atomicAdd(&cnt[batch[t]], 1.f);
}

__global__ void pool_sum_kernel(const float* __restrict__ h,
                                const int* __restrict__ batch,
                                float* __restrict__ gsum)
{
    int t = blockIdx.x * blockDim.x + threadIdx.x;
    if (t >= NN * FOUT) return;
    int n = t >> 7;
    int c = t & 127;
    atomicAdd(&gsum[batch[n] * FOUT + c], h[t]);
}

__global__ void pool_div_kernel(const float* __restrict__ gsum,
                                const float* __restrict__ cnt,
                                float* __restrict__ out)
{
    int t = blockIdx.x * blockDim.x + threadIdx.x;
    if (t >= GG * FOUT) return;
    out[t] = gsum[t] / fmaxf(cnt[t >> 7], 1.f);
}

// ---------------------------------------------------------------------------
// Launch
// ---------------------------------------------------------------------------
extern "C" void kernel_launch(void* const* d_in, const int* in_sizes, int n_in,
                              void* d_out, int out_size)
{
    const float* x   = (const float*)d_in[0];
    const int*   ei  = (const int*)d_in[1];
    const int*   bat = (const int*)d_in[2];
    const float* W1  = (const float*)d_in[3];
    const float* as1 = (const float*)d_in[4];
    const float* ad1 = (const float*)d_in[5];
    const float* b1  = (const float*)d_in[6];
    const float* W2  = (const float*)d_in[7];
    const float* as2 = (const float*)d_in[8];
    const float* ad2 = (const float*)d_in[9];
    const float* b2  = (const float*)d_in[10];
    const float* W3  = (const float*)d_in[11];
    const float* as3 = (const float*)d_in[12];
    const float* ad3 = (const float*)d_in[13];
    const float* b3  = (const float*)d_in[14];

    float* out     = (float*)d_out;
    float* out_emb = out;                 // [G, FOUT]
    float* out_h   = out + GG * FOUT;     // [N, FOUT]

    __half* h16;
    float *bufB, *as_, *ad_, *gsum, *gcnt;
    int *deg, *off, *cur, *csr_src;
    cudaGetSymbolAddress((void**)&h16,  g_h16);
    cudaGetSymbolAddress((void**)&bufB, g_bufB);
    cudaGetSymbolAddress((void**)&as_,  g_as);
    cudaGetSymbolAddress((void**)&ad_,  g_ad);
    cudaGetSymbolAddress((void**)&gsum, g_gsum);
    cudaGetSymbolAddress((void**)&gcnt, g_gcnt);
    cudaGetSymbolAddress((void**)&deg,  g_deg);
    cudaGetSymbolAddress((void**)&off,  g_off);
    cudaGetSymbolAddress((void**)&cur,  g_cur);
    cudaGetSymbolAddress((void**)&csr_src, g_csr_src);

    // --- CSR build ---
    cudaMemsetAsync(deg, 0, NN * sizeof(int));
    csr_count_kernel<<<(ETOT + 255) / 256, 256>>>(ei, deg);
    csr_scan_kernel<<<1, 1024>>>(deg, off, cur);
    csr_scatter_kernel<<<(ETOT + 255) / 256, 256>>>(ei, cur, csr_src);

    const int nby = (NN + 127) / 128;
    const int gatherGrid = (NN * 32 + 255) / 256;

    // --- Layer 1 ---
    gemm_tc_kernel<<<dim3(HC12 / 64, nby), 256>>>(x, W1, h16, NN, FIN, HC12);
    alpha_kernel<<<(NN * HEADS * 32 + 255) / 256, 256>>>(h16, as1, ad1, as_, ad_, HEADS, HID);
    gat_gather4_kernel<<<gatherGrid, 256>>>(off, csr_src, h16, as_, ad_, b1, bufB, 1);

    // --- Layer 2 ---
    gemm_tc_kernel<<<dim3(HC12 / 64, nby), 256>>>(bufB, W2, h16, NN, HC12, HC12);
    alpha_kernel<<<(NN * HEADS * 32 + 255) / 256, 256>>>(h16, as2, ad2, as_, ad_, HEADS, HID);
    gat_gather4_kernel<<<gatherGrid, 256>>>(off, csr_src, h16, as_, ad_, b2, bufB, 1);

    // --- Layer 3 ---
    gemm_tc_kernel<<<dim3(FOUT / 64, nby), 256>>>(bufB, W3, h16, NN, HC12, FOUT);
    alpha_kernel<<<(NN * 32 + 255) / 256, 256>>>(h16, as3, ad3, as_, ad_, 1, FOUT);
    gat_gather1_kernel<<<gatherGrid, 256>>>(off, csr_src, h16, as_, ad_, b3, out_h);

    // --- Global mean pool ---
    cudaMemsetAsync(gsum, 0, GG * FOUT * sizeof(float));
    cudaMemsetAsync(gcnt, 0, GG * sizeof(float));
    pool_cnt_kernel<<<(NN + 255) / 256, 256>>>(bat, gcnt);
    pool_sum_kernel<<<(NN * FOUT + 255) / 256, 256>>>(out_h, bat, gsum);
    pool_div_kernel<<<(GG * FOUT + 255) / 256, 256>>>(gsum, gcnt, out_emb);
}